// round 6
// baseline (speedup 1.0000x reference)
#include <cuda_runtime.h>
#include <cuda_fp16.h>
#include <stdint.h>

#define N_NODES_MAX 100000
#define IN_FEAT 64
#define OUT_FEAT 64
#define NUM_BASES 4
#define NUM_RELS 8
#define P2_COLS (NUM_RELS * OUT_FEAT)      // 512
#define WCAT_COLS (P2_COLS + OUT_FEAT)     // 576 (cols 512..575 = self-loop)

// Scratch: per-(node, relation) combined projections, fp16 [N, 8, 64] (~102.4 MB)
__device__ __half g_proj2[(size_t)N_NODES_MAX * P2_COLS];
// Combined weight matrix [64, 576] fp16
__device__ __half g_wcat[IN_FEAT * WCAT_COLS];

// ---------------------------------------------------------------------------
// Kernel 0: build Wcat (tiny)
// ---------------------------------------------------------------------------
__global__ void wcat_kernel(const float* __restrict__ weight,
                            const float* __restrict__ w_comp,
                            const float* __restrict__ loop_w)
{
    int idx = blockIdx.x * blockDim.x + threadIdx.x;
    if (idx >= IN_FEAT * WCAT_COLS) return;
    int k = idx / WCAT_COLS;
    int n = idx % WCAT_COLS;
    float v;
    if (n < P2_COLS) {
        int r = n >> 6, o = n & 63;
        v = 0.0f;
        #pragma unroll
        for (int b = 0; b < NUM_BASES; ++b)
            v += w_comp[r * NUM_BASES + b] * weight[((size_t)b * 64 + k) * 64 + o];
    } else {
        v = loop_w[(size_t)k * 64 + (n - P2_COLS)];
    }
    g_wcat[idx] = __float2half_rn(v);
}

// ---------------------------------------------------------------------------
// mma.sync helpers
// ---------------------------------------------------------------------------
__device__ __forceinline__ uint32_t smem_u32(const void* p) {
    return (uint32_t)__cvta_generic_to_shared(p);
}

#define LDSM_X4(r0, r1, r2, r3, addr)                                          \
    asm volatile("ldmatrix.sync.aligned.m8n8.x4.shared.b16 {%0,%1,%2,%3}, [%4];" \
                 : "=r"(r0), "=r"(r1), "=r"(r2), "=r"(r3) : "r"(addr))

#define LDSM_X4_T(r0, r1, r2, r3, addr)                                        \
    asm volatile("ldmatrix.sync.aligned.m8n8.x4.trans.shared.b16 {%0,%1,%2,%3}, [%4];" \
                 : "=r"(r0), "=r"(r1), "=r"(r2), "=r"(r3) : "r"(addr))

#define MMA_16816(d, a, b)                                                     \
    asm volatile("mma.sync.aligned.m16n8k16.row.col.f32.f16.f16.f32 "          \
                 "{%0,%1,%2,%3}, {%4,%5,%6,%7}, {%8,%9}, {%0,%1,%2,%3};"       \
                 : "+f"(d[0]), "+f"(d[1]), "+f"(d[2]), "+f"(d[3])              \
                 : "r"(a[0]), "r"(a[1]), "r"(a[2]), "r"(a[3]),                 \
                   "r"(b[0]), "r"(b[1]))

// ---------------------------------------------------------------------------
// Kernel A: proj2 (fp16) + out-init (fp32) via HMMA  (UNCHANGED from R5)
// ---------------------------------------------------------------------------
#define SA_STRIDE 72
#define SB_STRIDE 72

__global__ __launch_bounds__(256) void rgcn_mma_kernel(
    const float* __restrict__ feat,      // [N, 64]
    const float* __restrict__ h_bias,    // [64]
    float* __restrict__ out,             // [N, 64]
    int n_nodes)
{
    __shared__ __align__(16) __half sA[128 * SA_STRIDE];
    __shared__ __align__(16) __half sB[64 * SB_STRIDE];

    const int tid = threadIdx.x;
    const int row0 = blockIdx.x * 128;

    #pragma unroll
    for (int i = tid; i < 128 * 32; i += 256) {
        int r = i >> 5;
        int cp = i & 31;
        int row = row0 + r;
        float2 f = (row < n_nodes)
                     ? *(const float2*)&feat[(size_t)row * IN_FEAT + cp * 2]
                     : make_float2(0.0f, 0.0f);
        *(__half2*)&sA[r * SA_STRIDE + cp * 2] = __floats2half2_rn(f.x, f.y);
    }

    const int warp = tid >> 5;
    const int lane = tid & 31;
    const int wr = warp >> 1;
    const int wc = warp & 1;

    const int lrow = lane & 15;
    const int lcol = (lane >> 4) << 3;

    const int g   = lane >> 2;
    const int tig = lane & 3;

    for (int cp = 0; cp < 9; ++cp) {
        __syncthreads();
        #pragma unroll
        for (int i = tid; i < 64 * 32; i += 256) {
            int r = i >> 5;
            int c2 = i & 31;
            *(__half2*)&sB[r * SB_STRIDE + c2 * 2] =
                *(const __half2*)&g_wcat[(size_t)r * WCAT_COLS + cp * 64 + c2 * 2];
        }
        __syncthreads();

        float acc[2][4][4];
        #pragma unroll
        for (int mi = 0; mi < 2; ++mi)
            #pragma unroll
            for (int nj = 0; nj < 4; ++nj)
                #pragma unroll
                for (int q = 0; q < 4; ++q)
                    acc[mi][nj][q] = 0.0f;

        #pragma unroll
        for (int ks = 0; ks < 4; ++ks) {
            uint32_t a[2][4];
            #pragma unroll
            for (int mi = 0; mi < 2; ++mi) {
                const __half* p = &sA[(wr * 32 + mi * 16 + lrow) * SA_STRIDE
                                      + ks * 16 + lcol];
                LDSM_X4(a[mi][0], a[mi][1], a[mi][2], a[mi][3], smem_u32(p));
            }
            uint32_t b[4][2];
            #pragma unroll
            for (int np = 0; np < 2; ++np) {
                const __half* p = &sB[(ks * 16 + lrow) * SB_STRIDE
                                      + wc * 32 + np * 16 + lcol];
                uint32_t r0, r1, r2, r3;
                LDSM_X4_T(r0, r1, r2, r3, smem_u32(p));
                b[np * 2 + 0][0] = r0; b[np * 2 + 0][1] = r1;
                b[np * 2 + 1][0] = r2; b[np * 2 + 1][1] = r3;
            }
            #pragma unroll
            for (int mi = 0; mi < 2; ++mi)
                #pragma unroll
                for (int nj = 0; nj < 4; ++nj)
                    MMA_16816(acc[mi][nj], a[mi], b[nj]);
        }

        if (cp < 8) {
            #pragma unroll
            for (int mi = 0; mi < 2; ++mi) {
                int ra = row0 + wr * 32 + mi * 16 + g;
                int rb = ra + 8;
                #pragma unroll
                for (int nj = 0; nj < 4; ++nj) {
                    int col = cp * 64 + wc * 32 + nj * 8 + tig * 2;
                    if (ra < n_nodes)
                        *(__half2*)&g_proj2[(size_t)ra * P2_COLS + col] =
                            __floats2half2_rn(acc[mi][nj][0], acc[mi][nj][1]);
                    if (rb < n_nodes)
                        *(__half2*)&g_proj2[(size_t)rb * P2_COLS + col] =
                            __floats2half2_rn(acc[mi][nj][2], acc[mi][nj][3]);
                }
            }
        } else {
            #pragma unroll
            for (int mi = 0; mi < 2; ++mi) {
                int ra = row0 + wr * 32 + mi * 16 + g;
                int rb = ra + 8;
                #pragma unroll
                for (int nj = 0; nj < 4; ++nj) {
                    int col = wc * 32 + nj * 8 + tig * 2;
                    float b0 = h_bias[col];
                    float b1 = h_bias[col + 1];
                    if (ra < n_nodes) {
                        out[(size_t)ra * OUT_FEAT + col]     = acc[mi][nj][0] + b0;
                        out[(size_t)ra * OUT_FEAT + col + 1] = acc[mi][nj][1] + b1;
                    }
                    if (rb < n_nodes) {
                        out[(size_t)rb * OUT_FEAT + col]     = acc[mi][nj][2] + b0;
                        out[(size_t)rb * OUT_FEAT + col + 1] = acc[mi][nj][3] + b1;
                    }
                }
            }
        }
    }
}

// ---------------------------------------------------------------------------
// Kernel B: edge gather/scale/scatter, 4 edges per 16-lane group (MLP=4).
//   Vectorized metadata loads (int4/float4), 4 independent gathers, 4 REDs.
// ---------------------------------------------------------------------------
__global__ __launch_bounds__(256) void rgcn_edge_kernel(
    const int* __restrict__ src,
    const int* __restrict__ dst,
    const int* __restrict__ etypes,
    const float* __restrict__ norm,      // [E, 1]
    float* __restrict__ out,             // [N, 64]
    int n_edges)
{
    int gidx = blockIdx.x * 256 + threadIdx.x;
    int group = gidx >> 4;          // 16-lane group
    int lane = gidx & 15;
    int e0 = group * 4;
    if (e0 >= n_edges) return;

    int ss[4], dd[4], tt[4];
    float nn[4];
    int cnt;

    if (e0 + 4 <= n_edges) {
        // e0 is a multiple of 4 -> 16B-aligned vector loads
        int4 s4 = __ldg((const int4*)(src + e0));
        int4 d4 = __ldg((const int4*)(dst + e0));
        int4 t4 = __ldg((const int4*)(etypes + e0));
        float4 n4 = __ldg((const float4*)(norm + e0));
        ss[0] = s4.x; ss[1] = s4.y; ss[2] = s4.z; ss[3] = s4.w;
        dd[0] = d4.x; dd[1] = d4.y; dd[2] = d4.z; dd[3] = d4.w;
        tt[0] = t4.x; tt[1] = t4.y; tt[2] = t4.z; tt[3] = t4.w;
        nn[0] = n4.x; nn[1] = n4.y; nn[2] = n4.z; nn[3] = n4.w;
        cnt = 4;
    } else {
        cnt = n_edges - e0;
        for (int u = 0; u < cnt; ++u) {
            ss[u] = __ldg(&src[e0 + u]);
            dd[u] = __ldg(&dst[e0 + u]);
            tt[u] = __ldg(&etypes[e0 + u]);
            nn[u] = __ldg(&norm[e0 + u]);
        }
    }

    // Independent gathers (MLP = 4)
    uint2 raw[4];
    #pragma unroll
    for (int u = 0; u < 4; ++u) {
        if (u < cnt) {
            const __half* p = g_proj2 +
                ((size_t)ss[u] * P2_COLS + tt[u] * OUT_FEAT + lane * 4);
            raw[u] = __ldg(reinterpret_cast<const uint2*>(p));
        }
    }

    #pragma unroll
    for (int u = 0; u < 4; ++u) {
        if (u < cnt) {
            __half2 h0 = *reinterpret_cast<__half2*>(&raw[u].x);
            __half2 h1 = *reinterpret_cast<__half2*>(&raw[u].y);
            float2 f0 = __half22float2(h0);
            float2 f1 = __half22float2(h1);
            float nm = nn[u];
            float4 m = make_float4(f0.x * nm, f0.y * nm, f1.x * nm, f1.y * nm);
            float* o = out + (size_t)dd[u] * OUT_FEAT + lane * 4;
            asm volatile("red.global.add.v4.f32 [%0], {%1, %2, %3, %4};"
                         :: "l"(o), "f"(m.x), "f"(m.y), "f"(m.z), "f"(m.w)
                         : "memory");
        }
    }
}

// ---------------------------------------------------------------------------
extern "C" void kernel_launch(void* const* d_in, const int* in_sizes, int n_in,
                              void* d_out, int out_size)
{
    const float* feat    = (const float*)d_in[0];
    const int*   src     = (const int*)d_in[1];
    const int*   dst     = (const int*)d_in[2];
    const int*   etypes  = (const int*)d_in[3];
    const float* norm    = (const float*)d_in[4];
    const float* weight  = (const float*)d_in[5];
    const float* w_comp  = (const float*)d_in[6];
    const float* h_bias  = (const float*)d_in[7];
    const float* loop_w  = (const float*)d_in[8];
    float*       out     = (float*)d_out;

    int n_nodes = in_sizes[0] / IN_FEAT;
    int n_edges = in_sizes[1];

    // Phase 0: combined weight matrix (fp16)
    wcat_kernel<<<(IN_FEAT * WCAT_COLS + 255) / 256, 256>>>(weight, w_comp, loop_w);

    // Phase 1: HMMA GEMM -> proj2 (fp16) + out init (fp32)
    int gemm_blocks = (n_nodes + 127) / 128;
    rgcn_mma_kernel<<<gemm_blocks, 256>>>(feat, h_bias, out, n_nodes);

    // Phase 2: edge message + aggregation (4 edges / 16-lane group)
    int groups = (n_edges + 3) / 4;
    long long total_threads = (long long)groups * 16;
    int edge_blocks = (int)((total_threads + 255) / 256);
    rgcn_edge_kernel<<<edge_blocks, 256>>>(src, dst, etypes, norm, out, n_edges);
}

// round 7
// speedup vs baseline: 1.1559x; 1.1559x over previous
#include <cuda_runtime.h>
#include <cuda_fp16.h>
#include <stdint.h>

#define N_NODES_MAX 100000
#define N_EDGES_MAX 1600000
#define IN_FEAT 64
#define OUT_FEAT 64
#define NUM_BASES 4
#define NUM_RELS 8
#define P2_COLS (NUM_RELS * OUT_FEAT)      // 512
#define WCAT_COLS (P2_COLS + OUT_FEAT)     // 576

#define SCAN_T 1024
#define SCAN_NB ((N_NODES_MAX + SCAN_T - 1) / SCAN_T)   // 98

// Scratch
__device__ __half g_proj2[(size_t)N_NODES_MAX * P2_COLS];   // ~102.4 MB
__device__ __half g_wcat[IN_FEAT * WCAT_COLS];
__device__ int    g_count[N_NODES_MAX];     // per-node in-degree
__device__ int    g_offset[N_NODES_MAX];    // exclusive prefix
__device__ int    g_cursor[N_NODES_MAX];    // scatter cursors
__device__ int    g_bsum[SCAN_NB];          // block sums for scan
__device__ int2   g_edata[N_EDGES_MAX];     // dst-sorted {src|etype<<20, norm}

// ---------------------------------------------------------------------------
// Kernel 0a: zero counts
// ---------------------------------------------------------------------------
__global__ void zero_kernel(int n_nodes)
{
    int i = blockIdx.x * blockDim.x + threadIdx.x;
    if (i < n_nodes) g_count[i] = 0;
}

// ---------------------------------------------------------------------------
// Kernel 0b: build Wcat (tiny)
// ---------------------------------------------------------------------------
__global__ void wcat_kernel(const float* __restrict__ weight,
                            const float* __restrict__ w_comp,
                            const float* __restrict__ loop_w)
{
    int idx = blockIdx.x * blockDim.x + threadIdx.x;
    if (idx >= IN_FEAT * WCAT_COLS) return;
    int k = idx / WCAT_COLS;
    int n = idx % WCAT_COLS;
    float v;
    if (n < P2_COLS) {
        int r = n >> 6, o = n & 63;
        v = 0.0f;
        #pragma unroll
        for (int b = 0; b < NUM_BASES; ++b)
            v += w_comp[r * NUM_BASES + b] * weight[((size_t)b * 64 + k) * 64 + o];
    } else {
        v = loop_w[(size_t)k * 64 + (n - P2_COLS)];
    }
    g_wcat[idx] = __float2half_rn(v);
}

// ---------------------------------------------------------------------------
// mma.sync helpers
// ---------------------------------------------------------------------------
__device__ __forceinline__ uint32_t smem_u32(const void* p) {
    return (uint32_t)__cvta_generic_to_shared(p);
}

#define LDSM_X4(r0, r1, r2, r3, addr)                                          \
    asm volatile("ldmatrix.sync.aligned.m8n8.x4.shared.b16 {%0,%1,%2,%3}, [%4];" \
                 : "=r"(r0), "=r"(r1), "=r"(r2), "=r"(r3) : "r"(addr))

#define LDSM_X4_T(r0, r1, r2, r3, addr)                                        \
    asm volatile("ldmatrix.sync.aligned.m8n8.x4.trans.shared.b16 {%0,%1,%2,%3}, [%4];" \
                 : "=r"(r0), "=r"(r1), "=r"(r2), "=r"(r3) : "r"(addr))

#define MMA_16816(d, a, b)                                                     \
    asm volatile("mma.sync.aligned.m16n8k16.row.col.f32.f16.f16.f32 "          \
                 "{%0,%1,%2,%3}, {%4,%5,%6,%7}, {%8,%9}, {%0,%1,%2,%3};"       \
                 : "+f"(d[0]), "+f"(d[1]), "+f"(d[2]), "+f"(d[3])              \
                 : "r"(a[0]), "r"(a[1]), "r"(a[2]), "r"(a[3]),                 \
                   "r"(b[0]), "r"(b[1]))

// ---------------------------------------------------------------------------
// Kernel A: proj2 (fp16) + out-init (fp32) via HMMA  (UNCHANGED)
// ---------------------------------------------------------------------------
#define SA_STRIDE 72
#define SB_STRIDE 72

__global__ __launch_bounds__(256) void rgcn_mma_kernel(
    const float* __restrict__ feat,
    const float* __restrict__ h_bias,
    float* __restrict__ out,
    int n_nodes)
{
    __shared__ __align__(16) __half sA[128 * SA_STRIDE];
    __shared__ __align__(16) __half sB[64 * SB_STRIDE];

    const int tid = threadIdx.x;
    const int row0 = blockIdx.x * 128;

    #pragma unroll
    for (int i = tid; i < 128 * 32; i += 256) {
        int r = i >> 5;
        int cp = i & 31;
        int row = row0 + r;
        float2 f = (row < n_nodes)
                     ? *(const float2*)&feat[(size_t)row * IN_FEAT + cp * 2]
                     : make_float2(0.0f, 0.0f);
        *(__half2*)&sA[r * SA_STRIDE + cp * 2] = __floats2half2_rn(f.x, f.y);
    }

    const int warp = tid >> 5;
    const int lane = tid & 31;
    const int wr = warp >> 1;
    const int wc = warp & 1;
    const int lrow = lane & 15;
    const int lcol = (lane >> 4) << 3;
    const int g   = lane >> 2;
    const int tig = lane & 3;

    for (int cp = 0; cp < 9; ++cp) {
        __syncthreads();
        #pragma unroll
        for (int i = tid; i < 64 * 32; i += 256) {
            int r = i >> 5;
            int c2 = i & 31;
            *(__half2*)&sB[r * SB_STRIDE + c2 * 2] =
                *(const __half2*)&g_wcat[(size_t)r * WCAT_COLS + cp * 64 + c2 * 2];
        }
        __syncthreads();

        float acc[2][4][4];
        #pragma unroll
        for (int mi = 0; mi < 2; ++mi)
            #pragma unroll
            for (int nj = 0; nj < 4; ++nj)
                #pragma unroll
                for (int q = 0; q < 4; ++q)
                    acc[mi][nj][q] = 0.0f;

        #pragma unroll
        for (int ks = 0; ks < 4; ++ks) {
            uint32_t a[2][4];
            #pragma unroll
            for (int mi = 0; mi < 2; ++mi) {
                const __half* p = &sA[(wr * 32 + mi * 16 + lrow) * SA_STRIDE
                                      + ks * 16 + lcol];
                LDSM_X4(a[mi][0], a[mi][1], a[mi][2], a[mi][3], smem_u32(p));
            }
            uint32_t b[4][2];
            #pragma unroll
            for (int np = 0; np < 2; ++np) {
                const __half* p = &sB[(ks * 16 + lrow) * SB_STRIDE
                                      + wc * 32 + np * 16 + lcol];
                uint32_t r0, r1, r2, r3;
                LDSM_X4_T(r0, r1, r2, r3, smem_u32(p));
                b[np * 2 + 0][0] = r0; b[np * 2 + 0][1] = r1;
                b[np * 2 + 1][0] = r2; b[np * 2 + 1][1] = r3;
            }
            #pragma unroll
            for (int mi = 0; mi < 2; ++mi)
                #pragma unroll
                for (int nj = 0; nj < 4; ++nj)
                    MMA_16816(acc[mi][nj], a[mi], b[nj]);
        }

        if (cp < 8) {
            #pragma unroll
            for (int mi = 0; mi < 2; ++mi) {
                int ra = row0 + wr * 32 + mi * 16 + g;
                int rb = ra + 8;
                #pragma unroll
                for (int nj = 0; nj < 4; ++nj) {
                    int col = cp * 64 + wc * 32 + nj * 8 + tig * 2;
                    if (ra < n_nodes)
                        *(__half2*)&g_proj2[(size_t)ra * P2_COLS + col] =
                            __floats2half2_rn(acc[mi][nj][0], acc[mi][nj][1]);
                    if (rb < n_nodes)
                        *(__half2*)&g_proj2[(size_t)rb * P2_COLS + col] =
                            __floats2half2_rn(acc[mi][nj][2], acc[mi][nj][3]);
                }
            }
        } else {
            #pragma unroll
            for (int mi = 0; mi < 2; ++mi) {
                int ra = row0 + wr * 32 + mi * 16 + g;
                int rb = ra + 8;
                #pragma unroll
                for (int nj = 0; nj < 4; ++nj) {
                    int col = wc * 32 + nj * 8 + tig * 2;
                    float b0 = h_bias[col];
                    float b1 = h_bias[col + 1];
                    if (ra < n_nodes) {
                        out[(size_t)ra * OUT_FEAT + col]     = acc[mi][nj][0] + b0;
                        out[(size_t)ra * OUT_FEAT + col + 1] = acc[mi][nj][1] + b1;
                    }
                    if (rb < n_nodes) {
                        out[(size_t)rb * OUT_FEAT + col]     = acc[mi][nj][2] + b0;
                        out[(size_t)rb * OUT_FEAT + col + 1] = acc[mi][nj][3] + b1;
                    }
                }
            }
        }
    }
}

// ---------------------------------------------------------------------------
// Kernel 1: histogram of dst
// ---------------------------------------------------------------------------
__global__ void hist_kernel(const int* __restrict__ dst, int n_edges)
{
    int e = blockIdx.x * blockDim.x + threadIdx.x;
    if (e < n_edges) atomicAdd(&g_count[__ldg(&dst[e])], 1);
}

// ---------------------------------------------------------------------------
// Kernels 2a/2b/2c: exclusive scan over g_count -> g_offset (+ cursors)
// ---------------------------------------------------------------------------
__global__ __launch_bounds__(SCAN_T) void scan_local_kernel(int n_nodes)
{
    __shared__ int sh[SCAN_T];
    int i = blockIdx.x * SCAN_T + threadIdx.x;
    int c = (i < n_nodes) ? g_count[i] : 0;
    sh[threadIdx.x] = c;
    __syncthreads();
    #pragma unroll
    for (int off = 1; off < SCAN_T; off <<= 1) {
        int v = (threadIdx.x >= off) ? sh[threadIdx.x - off] : 0;
        __syncthreads();
        sh[threadIdx.x] += v;
        __syncthreads();
    }
    if (i < n_nodes) g_offset[i] = sh[threadIdx.x] - c;   // exclusive
    if (threadIdx.x == SCAN_T - 1) g_bsum[blockIdx.x] = sh[SCAN_T - 1];
}

__global__ __launch_bounds__(128) void scan_bsum_kernel(int nb)
{
    __shared__ int sh[128];
    int t = threadIdx.x;
    int c = (t < nb) ? g_bsum[t] : 0;
    sh[t] = c;
    __syncthreads();
    #pragma unroll
    for (int off = 1; off < 128; off <<= 1) {
        int v = (t >= off) ? sh[t - off] : 0;
        __syncthreads();
        sh[t] += v;
        __syncthreads();
    }
    if (t < nb) g_bsum[t] = sh[t] - c;   // exclusive block bases
}

__global__ __launch_bounds__(SCAN_T) void scan_add_kernel(int n_nodes)
{
    int i = blockIdx.x * SCAN_T + threadIdx.x;
    if (i < n_nodes) {
        int o = g_offset[i] + g_bsum[blockIdx.x];
        g_offset[i] = o;
        g_cursor[i] = o;
    }
}

// ---------------------------------------------------------------------------
// Kernel 3: scatter edges into dst-sorted order with packed payload
//   g_edata[pos] = { src | etype<<20, norm }
// ---------------------------------------------------------------------------
__global__ void scatter_kernel(const int* __restrict__ src,
                               const int* __restrict__ dst,
                               const int* __restrict__ etypes,
                               const float* __restrict__ norm,
                               int n_edges)
{
    int e = blockIdx.x * blockDim.x + threadIdx.x;
    if (e >= n_edges) return;
    int d = __ldg(&dst[e]);
    int s = __ldg(&src[e]);
    int t = __ldg(&etypes[e]);
    float nm = __ldg(&norm[e]);
    int pos = atomicAdd(&g_cursor[d], 1);
    g_edata[pos] = make_int2(s | (t << 20), __float_as_int(nm));
}

// ---------------------------------------------------------------------------
// Kernel 4: per-node aggregation (no atomics)
//   16 lanes per node; acc initialized from out (bias+selfloop), one store.
// ---------------------------------------------------------------------------
__global__ __launch_bounds__(256) void agg_kernel(
    float* __restrict__ out, int n_nodes)
{
    int gidx = blockIdx.x * 256 + threadIdx.x;
    int node = gidx >> 4;
    int lane = gidx & 15;
    if (node >= n_nodes) return;

    int start = __ldg(&g_offset[node]);
    int deg   = __ldg(&g_count[node]);

    float4 acc = *(float4*)&out[(size_t)node * OUT_FEAT + lane * 4];

    int j = 0;
    for (; j + 4 <= deg; j += 4) {
        int2 e0 = __ldg(&g_edata[start + j + 0]);
        int2 e1 = __ldg(&g_edata[start + j + 1]);
        int2 e2 = __ldg(&g_edata[start + j + 2]);
        int2 e3 = __ldg(&g_edata[start + j + 3]);
        uint2 r0 = __ldg((const uint2*)(g_proj2 +
            ((size_t)(e0.x & 0xFFFFF) * P2_COLS + (e0.x >> 20) * OUT_FEAT + lane * 4)));
        uint2 r1 = __ldg((const uint2*)(g_proj2 +
            ((size_t)(e1.x & 0xFFFFF) * P2_COLS + (e1.x >> 20) * OUT_FEAT + lane * 4)));
        uint2 r2 = __ldg((const uint2*)(g_proj2 +
            ((size_t)(e2.x & 0xFFFFF) * P2_COLS + (e2.x >> 20) * OUT_FEAT + lane * 4)));
        uint2 r3 = __ldg((const uint2*)(g_proj2 +
            ((size_t)(e3.x & 0xFFFFF) * P2_COLS + (e3.x >> 20) * OUT_FEAT + lane * 4)));
        {
            float nm = __int_as_float(e0.y);
            float2 f0 = __half22float2(*reinterpret_cast<__half2*>(&r0.x));
            float2 f1 = __half22float2(*reinterpret_cast<__half2*>(&r0.y));
            acc.x += f0.x * nm; acc.y += f0.y * nm; acc.z += f1.x * nm; acc.w += f1.y * nm;
        }
        {
            float nm = __int_as_float(e1.y);
            float2 f0 = __half22float2(*reinterpret_cast<__half2*>(&r1.x));
            float2 f1 = __half22float2(*reinterpret_cast<__half2*>(&r1.y));
            acc.x += f0.x * nm; acc.y += f0.y * nm; acc.z += f1.x * nm; acc.w += f1.y * nm;
        }
        {
            float nm = __int_as_float(e2.y);
            float2 f0 = __half22float2(*reinterpret_cast<__half2*>(&r2.x));
            float2 f1 = __half22float2(*reinterpret_cast<__half2*>(&r2.y));
            acc.x += f0.x * nm; acc.y += f0.y * nm; acc.z += f1.x * nm; acc.w += f1.y * nm;
        }
        {
            float nm = __int_as_float(e3.y);
            float2 f0 = __half22float2(*reinterpret_cast<__half2*>(&r3.x));
            float2 f1 = __half22float2(*reinterpret_cast<__half2*>(&r3.y));
            acc.x += f0.x * nm; acc.y += f0.y * nm; acc.z += f1.x * nm; acc.w += f1.y * nm;
        }
    }
    for (; j < deg; ++j) {
        int2 ed = __ldg(&g_edata[start + j]);
        uint2 raw = __ldg((const uint2*)(g_proj2 +
            ((size_t)(ed.x & 0xFFFFF) * P2_COLS + (ed.x >> 20) * OUT_FEAT + lane * 4)));
        float nm = __int_as_float(ed.y);
        float2 f0 = __half22float2(*reinterpret_cast<__half2*>(&raw.x));
        float2 f1 = __half22float2(*reinterpret_cast<__half2*>(&raw.y));
        acc.x += f0.x * nm; acc.y += f0.y * nm; acc.z += f1.x * nm; acc.w += f1.y * nm;
    }

    *(float4*)&out[(size_t)node * OUT_FEAT + lane * 4] = acc;
}

// ---------------------------------------------------------------------------
extern "C" void kernel_launch(void* const* d_in, const int* in_sizes, int n_in,
                              void* d_out, int out_size)
{
    const float* feat    = (const float*)d_in[0];
    const int*   src     = (const int*)d_in[1];
    const int*   dst     = (const int*)d_in[2];
    const int*   etypes  = (const int*)d_in[3];
    const float* norm    = (const float*)d_in[4];
    const float* weight  = (const float*)d_in[5];
    const float* w_comp  = (const float*)d_in[6];
    const float* h_bias  = (const float*)d_in[7];
    const float* loop_w  = (const float*)d_in[8];
    float*       out     = (float*)d_out;

    int n_nodes = in_sizes[0] / IN_FEAT;
    int n_edges = in_sizes[1];

    // Phase 0: reset counters + combined weights
    zero_kernel<<<(n_nodes + 255) / 256, 256>>>(n_nodes);
    wcat_kernel<<<(IN_FEAT * WCAT_COLS + 255) / 256, 256>>>(weight, w_comp, loop_w);

    // Phase 1: HMMA GEMM -> proj2 (fp16) + out init (fp32)
    rgcn_mma_kernel<<<(n_nodes + 127) / 128, 256>>>(feat, h_bias, out, n_nodes);

    // Phase 2: counting sort of edges by dst
    hist_kernel<<<(n_edges + 255) / 256, 256>>>(dst, n_edges);
    int nb = (n_nodes + SCAN_T - 1) / SCAN_T;
    scan_local_kernel<<<nb, SCAN_T>>>(n_nodes);
    scan_bsum_kernel<<<1, 128>>>(nb);
    scan_add_kernel<<<nb, SCAN_T>>>(n_nodes);
    scatter_kernel<<<(n_edges + 255) / 256, 256>>>(src, dst, etypes, norm, n_edges);

    // Phase 3: per-node aggregation (atomic-free)
    long long total_threads = (long long)n_nodes * 16;
    agg_kernel<<<(int)((total_threads + 255) / 256), 256>>>(out, n_nodes);
}

// round 8
// speedup vs baseline: 1.2018x; 1.0397x over previous
#include <cuda_runtime.h>
#include <cuda_fp16.h>
#include <stdint.h>

#define N_NODES_MAX 100000
#define N_EDGES_MAX 1600000
#define IN_FEAT 64
#define OUT_FEAT 64
#define NUM_BASES 4
#define NUM_RELS 8
#define P2_COLS (NUM_RELS * OUT_FEAT)      // 512
#define WCAT_COLS (P2_COLS + OUT_FEAT)     // 576

#define SCAN_T 1024
#define SCAN_NB ((N_NODES_MAX + SCAN_T - 1) / SCAN_T)

// Scratch
__device__ __half g_proj2[(size_t)N_NODES_MAX * P2_COLS];   // ~102.4 MB
__device__ __half g_wcat[IN_FEAT * WCAT_COLS];
__device__ int    g_count[N_NODES_MAX];
__device__ int    g_offset[N_NODES_MAX];
__device__ int    g_cursor[N_NODES_MAX];
__device__ int    g_bsum[SCAN_NB];
__device__ int2   g_edata[N_EDGES_MAX];     // dst-sorted {src|etype<<20, norm}

// ---------------------------------------------------------------------------
__global__ void zero_kernel(int n_nodes)
{
    int i = blockIdx.x * blockDim.x + threadIdx.x;
    if (i < n_nodes) g_count[i] = 0;
}

__global__ void wcat_kernel(const float* __restrict__ weight,
                            const float* __restrict__ w_comp,
                            const float* __restrict__ loop_w)
{
    int idx = blockIdx.x * blockDim.x + threadIdx.x;
    if (idx >= IN_FEAT * WCAT_COLS) return;
    int k = idx / WCAT_COLS;
    int n = idx % WCAT_COLS;
    float v;
    if (n < P2_COLS) {
        int r = n >> 6, o = n & 63;
        v = 0.0f;
        #pragma unroll
        for (int b = 0; b < NUM_BASES; ++b)
            v += w_comp[r * NUM_BASES + b] * weight[((size_t)b * 64 + k) * 64 + o];
    } else {
        v = loop_w[(size_t)k * 64 + (n - P2_COLS)];
    }
    g_wcat[idx] = __float2half_rn(v);
}

// ---------------------------------------------------------------------------
__device__ __forceinline__ uint32_t smem_u32(const void* p) {
    return (uint32_t)__cvta_generic_to_shared(p);
}

#define LDSM_X4(r0, r1, r2, r3, addr)                                          \
    asm volatile("ldmatrix.sync.aligned.m8n8.x4.shared.b16 {%0,%1,%2,%3}, [%4];" \
                 : "=r"(r0), "=r"(r1), "=r"(r2), "=r"(r3) : "r"(addr))

#define LDSM_X4_T(r0, r1, r2, r3, addr)                                        \
    asm volatile("ldmatrix.sync.aligned.m8n8.x4.trans.shared.b16 {%0,%1,%2,%3}, [%4];" \
                 : "=r"(r0), "=r"(r1), "=r"(r2), "=r"(r3) : "r"(addr))

#define MMA_16816(d, a, b)                                                     \
    asm volatile("mma.sync.aligned.m16n8k16.row.col.f32.f16.f16.f32 "          \
                 "{%0,%1,%2,%3}, {%4,%5,%6,%7}, {%8,%9}, {%0,%1,%2,%3};"       \
                 : "+f"(d[0]), "+f"(d[1]), "+f"(d[2]), "+f"(d[3])              \
                 : "r"(a[0]), "r"(a[1]), "r"(a[2]), "r"(a[3]),                 \
                   "r"(b[0]), "r"(b[1]))

// ---------------------------------------------------------------------------
// Kernel A: proj2 (fp16) + out-init (fp32) via HMMA.
//   - whole Wcat preloaded in smem (one load, no per-pass reload)
//   - proj2 tile staged in smem -> coalesced STG.128 copy-out
// Dynamic smem: sA 128x72h | sB 64x584h | sS 128x72h
// ---------------------------------------------------------------------------
#define SA_STRIDE 72
#define SB_STRIDE 584   // 576 + 8 pad: row stride 1168B, mod 128 = 16 -> conflict-free
#define SS_STRIDE 72

#define SMEM_A_OFF 0
#define SMEM_B_OFF (128 * SA_STRIDE)
#define SMEM_S_OFF (128 * SA_STRIDE + 64 * SB_STRIDE)
#define SMEM_HALVES (128 * SA_STRIDE + 64 * SB_STRIDE + 128 * SS_STRIDE)
#define SMEM_BYTES (SMEM_HALVES * 2)

__global__ __launch_bounds__(256) void rgcn_mma_kernel(
    const float* __restrict__ feat,
    const float* __restrict__ h_bias,
    float* __restrict__ out,
    int n_nodes)
{
    extern __shared__ __align__(16) __half dyn[];
    __half* sA = dyn + SMEM_A_OFF;
    __half* sB = dyn + SMEM_B_OFF;
    __half* sS = dyn + SMEM_S_OFF;

    const int tid = threadIdx.x;
    const int row0 = blockIdx.x * 128;

    // Load A tile (128 x 64), fp32 -> fp16
    #pragma unroll
    for (int i = tid; i < 128 * 32; i += 256) {
        int r = i >> 5;
        int cpair = i & 31;
        int row = row0 + r;
        float2 f = (row < n_nodes)
                     ? *(const float2*)&feat[(size_t)row * IN_FEAT + cpair * 2]
                     : make_float2(0.0f, 0.0f);
        *(__half2*)&sA[r * SA_STRIDE + cpair * 2] = __floats2half2_rn(f.x, f.y);
    }
    // Load full Wcat (64 x 576)
    #pragma unroll
    for (int i = tid; i < 64 * 288; i += 256) {
        int r = i / 288;
        int c2 = i % 288;
        *(__half2*)&sB[r * SB_STRIDE + c2 * 2] =
            *(const __half2*)&g_wcat[(size_t)r * WCAT_COLS + c2 * 2];
    }
    __syncthreads();

    const int warp = tid >> 5;
    const int lane = tid & 31;
    const int wr = warp >> 1;
    const int wc = warp & 1;
    const int lrow = lane & 15;
    const int lcol = (lane >> 4) << 3;
    const int g   = lane >> 2;
    const int tig = lane & 3;

    for (int cp = 0; cp < 9; ++cp) {
        float acc[2][4][4];
        #pragma unroll
        for (int mi = 0; mi < 2; ++mi)
            #pragma unroll
            for (int nj = 0; nj < 4; ++nj)
                #pragma unroll
                for (int q = 0; q < 4; ++q)
                    acc[mi][nj][q] = 0.0f;

        #pragma unroll
        for (int ks = 0; ks < 4; ++ks) {
            uint32_t a[2][4];
            #pragma unroll
            for (int mi = 0; mi < 2; ++mi) {
                const __half* p = &sA[(wr * 32 + mi * 16 + lrow) * SA_STRIDE
                                      + ks * 16 + lcol];
                LDSM_X4(a[mi][0], a[mi][1], a[mi][2], a[mi][3], smem_u32(p));
            }
            uint32_t b[4][2];
            #pragma unroll
            for (int np = 0; np < 2; ++np) {
                const __half* p = &sB[(ks * 16 + lrow) * SB_STRIDE
                                      + cp * 64 + wc * 32 + np * 16 + lcol];
                uint32_t r0, r1, r2, r3;
                LDSM_X4_T(r0, r1, r2, r3, smem_u32(p));
                b[np * 2 + 0][0] = r0; b[np * 2 + 0][1] = r1;
                b[np * 2 + 1][0] = r2; b[np * 2 + 1][1] = r3;
            }
            #pragma unroll
            for (int mi = 0; mi < 2; ++mi)
                #pragma unroll
                for (int nj = 0; nj < 4; ++nj)
                    MMA_16816(acc[mi][nj], a[mi], b[nj]);
        }

        if (cp < 8) {
            __syncthreads();   // prev copy-out done before overwriting stage
            #pragma unroll
            for (int mi = 0; mi < 2; ++mi) {
                int rta = wr * 32 + mi * 16 + g;
                int rtb = rta + 8;
                #pragma unroll
                for (int nj = 0; nj < 4; ++nj) {
                    int col = wc * 32 + nj * 8 + tig * 2;
                    *(__half2*)&sS[rta * SS_STRIDE + col] =
                        __floats2half2_rn(acc[mi][nj][0], acc[mi][nj][1]);
                    *(__half2*)&sS[rtb * SS_STRIDE + col] =
                        __floats2half2_rn(acc[mi][nj][2], acc[mi][nj][3]);
                }
            }
            __syncthreads();
            // Coalesced copy-out: 128 rows x 128B, 16B per thread x 4
            #pragma unroll
            for (int i = tid; i < 1024; i += 256) {
                int r = i >> 3;          // row in tile
                int ch = i & 7;          // 16B chunk
                int row = row0 + r;
                if (row < n_nodes) {
                    uint4 v = *(const uint4*)&sS[r * SS_STRIDE + ch * 8];
                    *(uint4*)&g_proj2[(size_t)row * P2_COLS + cp * OUT_FEAT + ch * 8] = v;
                }
            }
        } else {
            // self-loop pass: direct fp32 stores (float2)
            #pragma unroll
            for (int mi = 0; mi < 2; ++mi) {
                int ra = row0 + wr * 32 + mi * 16 + g;
                int rb = ra + 8;
                #pragma unroll
                for (int nj = 0; nj < 4; ++nj) {
                    int col = wc * 32 + nj * 8 + tig * 2;
                    float b0 = h_bias[col];
                    float b1 = h_bias[col + 1];
                    if (ra < n_nodes)
                        *(float2*)&out[(size_t)ra * OUT_FEAT + col] =
                            make_float2(acc[mi][nj][0] + b0, acc[mi][nj][1] + b1);
                    if (rb < n_nodes)
                        *(float2*)&out[(size_t)rb * OUT_FEAT + col] =
                            make_float2(acc[mi][nj][2] + b0, acc[mi][nj][3] + b1);
                }
            }
        }
    }
}

// ---------------------------------------------------------------------------
// Kernel 1: histogram of dst (4 edges/thread, int4)
// ---------------------------------------------------------------------------
__global__ void hist_kernel(const int* __restrict__ dst, int n_edges)
{
    int i = blockIdx.x * blockDim.x + threadIdx.x;
    int e0 = i * 4;
    if (e0 + 4 <= n_edges) {
        int4 d = __ldg((const int4*)(dst + e0));
        atomicAdd(&g_count[d.x], 1);
        atomicAdd(&g_count[d.y], 1);
        atomicAdd(&g_count[d.z], 1);
        atomicAdd(&g_count[d.w], 1);
    } else if (e0 < n_edges) {
        for (int e = e0; e < n_edges; ++e)
            atomicAdd(&g_count[__ldg(&dst[e])], 1);
    }
}

// ---------------------------------------------------------------------------
// Scan kernels (unchanged)
// ---------------------------------------------------------------------------
__global__ __launch_bounds__(SCAN_T) void scan_local_kernel(int n_nodes)
{
    __shared__ int sh[SCAN_T];
    int i = blockIdx.x * SCAN_T + threadIdx.x;
    int c = (i < n_nodes) ? g_count[i] : 0;
    sh[threadIdx.x] = c;
    __syncthreads();
    #pragma unroll
    for (int off = 1; off < SCAN_T; off <<= 1) {
        int v = (threadIdx.x >= off) ? sh[threadIdx.x - off] : 0;
        __syncthreads();
        sh[threadIdx.x] += v;
        __syncthreads();
    }
    if (i < n_nodes) g_offset[i] = sh[threadIdx.x] - c;
    if (threadIdx.x == SCAN_T - 1) g_bsum[blockIdx.x] = sh[SCAN_T - 1];
}

__global__ __launch_bounds__(128) void scan_bsum_kernel(int nb)
{
    __shared__ int sh[128];
    int t = threadIdx.x;
    int c = (t < nb) ? g_bsum[t] : 0;
    sh[t] = c;
    __syncthreads();
    #pragma unroll
    for (int off = 1; off < 128; off <<= 1) {
        int v = (t >= off) ? sh[t - off] : 0;
        __syncthreads();
        sh[t] += v;
        __syncthreads();
    }
    if (t < nb) g_bsum[t] = sh[t] - c;
}

__global__ __launch_bounds__(SCAN_T) void scan_add_kernel(int n_nodes)
{
    int i = blockIdx.x * SCAN_T + threadIdx.x;
    if (i < n_nodes) {
        int o = g_offset[i] + g_bsum[blockIdx.x];
        g_offset[i] = o;
        g_cursor[i] = o;
    }
}

// ---------------------------------------------------------------------------
// Kernel 3: scatter edges into dst-sorted order (4 edges/thread)
// ---------------------------------------------------------------------------
__global__ void scatter_kernel(const int* __restrict__ src,
                               const int* __restrict__ dst,
                               const int* __restrict__ etypes,
                               const float* __restrict__ norm,
                               int n_edges)
{
    int i = blockIdx.x * blockDim.x + threadIdx.x;
    int e0 = i * 4;
    if (e0 + 4 <= n_edges) {
        int4 s = __ldg((const int4*)(src + e0));
        int4 d = __ldg((const int4*)(dst + e0));
        int4 t = __ldg((const int4*)(etypes + e0));
        float4 nm = __ldg((const float4*)(norm + e0));
        int p0 = atomicAdd(&g_cursor[d.x], 1);
        int p1 = atomicAdd(&g_cursor[d.y], 1);
        int p2 = atomicAdd(&g_cursor[d.z], 1);
        int p3 = atomicAdd(&g_cursor[d.w], 1);
        g_edata[p0] = make_int2(s.x | (t.x << 20), __float_as_int(nm.x));
        g_edata[p1] = make_int2(s.y | (t.y << 20), __float_as_int(nm.y));
        g_edata[p2] = make_int2(s.z | (t.z << 20), __float_as_int(nm.z));
        g_edata[p3] = make_int2(s.w | (t.w << 20), __float_as_int(nm.w));
    } else if (e0 < n_edges) {
        for (int e = e0; e < n_edges; ++e) {
            int d = __ldg(&dst[e]);
            int pos = atomicAdd(&g_cursor[d], 1);
            g_edata[pos] = make_int2(__ldg(&src[e]) | (__ldg(&etypes[e]) << 20),
                                     __float_as_int(__ldg(&norm[e])));
        }
    }
}

// ---------------------------------------------------------------------------
// Kernel 4: per-node aggregation, 8 lanes/node, uint4 gathers (MLP=4)
// ---------------------------------------------------------------------------
__device__ __forceinline__ void acc_msg(float4& a, float4& b, uint4 raw, float nm)
{
    float2 f0 = __half22float2(*reinterpret_cast<__half2*>(&raw.x));
    float2 f1 = __half22float2(*reinterpret_cast<__half2*>(&raw.y));
    float2 f2 = __half22float2(*reinterpret_cast<__half2*>(&raw.z));
    float2 f3 = __half22float2(*reinterpret_cast<__half2*>(&raw.w));
    a.x += f0.x * nm; a.y += f0.y * nm; a.z += f1.x * nm; a.w += f1.y * nm;
    b.x += f2.x * nm; b.y += f2.y * nm; b.z += f3.x * nm; b.w += f3.y * nm;
}

__global__ __launch_bounds__(256) void agg_kernel(
    float* __restrict__ out, int n_nodes)
{
    int gidx = blockIdx.x * 256 + threadIdx.x;
    int node = gidx >> 3;
    int lane = gidx & 7;
    if (node >= n_nodes) return;

    int start = __ldg(&g_offset[node]);
    int deg   = __ldg(&g_count[node]);

    float4 accA = *(float4*)&out[(size_t)node * OUT_FEAT + lane * 8];
    float4 accB = *(float4*)&out[(size_t)node * OUT_FEAT + lane * 8 + 4];

    int j = 0;
    for (; j + 4 <= deg; j += 4) {
        int2 e0 = __ldg(&g_edata[start + j + 0]);
        int2 e1 = __ldg(&g_edata[start + j + 1]);
        int2 e2 = __ldg(&g_edata[start + j + 2]);
        int2 e3 = __ldg(&g_edata[start + j + 3]);
        uint4 r0 = __ldg((const uint4*)(g_proj2 +
            ((size_t)(e0.x & 0xFFFFF) * P2_COLS + (e0.x >> 20) * OUT_FEAT + lane * 8)));
        uint4 r1 = __ldg((const uint4*)(g_proj2 +
            ((size_t)(e1.x & 0xFFFFF) * P2_COLS + (e1.x >> 20) * OUT_FEAT + lane * 8)));
        uint4 r2 = __ldg((const uint4*)(g_proj2 +
            ((size_t)(e2.x & 0xFFFFF) * P2_COLS + (e2.x >> 20) * OUT_FEAT + lane * 8)));
        uint4 r3 = __ldg((const uint4*)(g_proj2 +
            ((size_t)(e3.x & 0xFFFFF) * P2_COLS + (e3.x >> 20) * OUT_FEAT + lane * 8)));
        acc_msg(accA, accB, r0, __int_as_float(e0.y));
        acc_msg(accA, accB, r1, __int_as_float(e1.y));
        acc_msg(accA, accB, r2, __int_as_float(e2.y));
        acc_msg(accA, accB, r3, __int_as_float(e3.y));
    }
    for (; j < deg; ++j) {
        int2 ed = __ldg(&g_edata[start + j]);
        uint4 raw = __ldg((const uint4*)(g_proj2 +
            ((size_t)(ed.x & 0xFFFFF) * P2_COLS + (ed.x >> 20) * OUT_FEAT + lane * 8)));
        acc_msg(accA, accB, raw, __int_as_float(ed.y));
    }

    *(float4*)&out[(size_t)node * OUT_FEAT + lane * 8]     = accA;
    *(float4*)&out[(size_t)node * OUT_FEAT + lane * 8 + 4] = accB;
}

// ---------------------------------------------------------------------------
extern "C" void kernel_launch(void* const* d_in, const int* in_sizes, int n_in,
                              void* d_out, int out_size)
{
    const float* feat    = (const float*)d_in[0];
    const int*   src     = (const int*)d_in[1];
    const int*   dst     = (const int*)d_in[2];
    const int*   etypes  = (const int*)d_in[3];
    const float* norm    = (const float*)d_in[4];
    const float* weight  = (const float*)d_in[5];
    const float* w_comp  = (const float*)d_in[6];
    const float* h_bias  = (const float*)d_in[7];
    const float* loop_w  = (const float*)d_in[8];
    float*       out     = (float*)d_out;

    int n_nodes = in_sizes[0] / IN_FEAT;
    int n_edges = in_sizes[1];

    cudaFuncSetAttribute(rgcn_mma_kernel,
                         cudaFuncAttributeMaxDynamicSharedMemorySize, SMEM_BYTES);

    // Phase 0
    zero_kernel<<<(n_nodes + 255) / 256, 256>>>(n_nodes);
    wcat_kernel<<<(IN_FEAT * WCAT_COLS + 255) / 256, 256>>>(weight, w_comp, loop_w);

    // Phase 1: HMMA GEMM
    rgcn_mma_kernel<<<(n_nodes + 127) / 128, 256, SMEM_BYTES>>>(feat, h_bias, out, n_nodes);

    // Phase 2: counting sort by dst
    int hthreads = (n_edges + 3) / 4;
    hist_kernel<<<(hthreads + 255) / 256, 256>>>(dst, n_edges);
    int nb = (n_nodes + SCAN_T - 1) / SCAN_T;
    scan_local_kernel<<<nb, SCAN_T>>>(n_nodes);
    scan_bsum_kernel<<<1, 128>>>(nb);
    scan_add_kernel<<<nb, SCAN_T>>>(n_nodes);
    scatter_kernel<<<(hthreads + 255) / 256, 256>>>(src, dst, etypes, norm, n_edges);

    // Phase 3: atomic-free aggregation
    long long total_threads = (long long)n_nodes * 8;
    agg_kernel<<<(int)((total_threads + 255) / 256), 256>>>(out, n_nodes);
}